// round 8
// baseline (speedup 1.0000x reference)
#include <cuda_runtime.h>
#include <cuda_bf16.h>
#include <math.h>
#include <stdint.h>

#define NWIN 512
#define NTOK 256
#define CH   96
#define NH   3
#define HD   32
#define HID  384
#define LDW  52    // stride (uint32) for 48-word operand rows (GEMM A/B, O_s)
#define LDV  20    // stride (uint32) for 16-word rows (K_s, V_s)
#define LOG2E 1.4426950408889634f

// Scratch (device globals)
__device__ float         g_t[(size_t)NWIN * NTOK * CH];       // residual fp32 [w][t][c]
__device__ __nv_bfloat16 g_q[(size_t)NWIN * NH * NTOK * HD];  // [t][d], pre-scaled
__device__ __nv_bfloat16 g_k[(size_t)NWIN * NH * NTOK * HD];
__device__ __nv_bfloat16 g_v[(size_t)NWIN * NH * NTOK * HD];
__device__ uint32_t      g_biasp[NH * NTOK * 128];            // bf16x2 [h][m][n/2], *log2e
// weights as bf16x2 pairs
__device__ uint32_t gw_qkv[288 * 48];
__device__ uint32_t gw_proj[96 * 48];
__device__ uint32_t gw_fc1[384 * 48];
__device__ uint32_t gw_fc2[96 * 192];

// ---------------------------------------------------------------------------
__device__ __forceinline__ void cp_async16(void* s, const void* g) {
    uint32_t sa = (uint32_t)__cvta_generic_to_shared(s);
    asm volatile("cp.async.cg.shared.global [%0], [%1], 16;" :: "r"(sa), "l"(g));
}
#define CP_COMMIT asm volatile("cp.async.commit_group;")
#define CP_WAIT0  asm volatile("cp.async.wait_group 0;")

__device__ __forceinline__ uint32_t s2u(const void* p) {
    return (uint32_t)__cvta_generic_to_shared(p);
}
__device__ __forceinline__ uint32_t pk(float a, float b) {
    __nv_bfloat162 h = __floats2bfloat162_rn(a, b);
    return *(uint32_t*)&h;
}
__device__ __forceinline__ float ex2(float x) {
    float y;
    asm("ex2.approx.ftz.f32 %0, %1;" : "=f"(y) : "f"(x));
    return y;
}
__device__ __forceinline__ void bmma(float* c, const uint32_t* a, uint32_t b0, uint32_t b1) {
    asm("mma.sync.aligned.m16n8k16.row.col.f32.bf16.bf16.f32 "
        "{%0,%1,%2,%3},{%4,%5,%6,%7},{%8,%9},{%0,%1,%2,%3};"
        : "+f"(c[0]), "+f"(c[1]), "+f"(c[2]), "+f"(c[3])
        : "r"(a[0]), "r"(a[1]), "r"(a[2]), "r"(a[3]), "r"(b0), "r"(b1));
}
__device__ __forceinline__ void ldsm4(uint32_t* r, uint32_t a) {
    asm volatile("ldmatrix.sync.aligned.m8n8.x4.shared.b16 {%0,%1,%2,%3},[%4];"
        : "=r"(r[0]), "=r"(r[1]), "=r"(r[2]), "=r"(r[3]) : "r"(a));
}
__device__ __forceinline__ void ldsm4t(uint32_t* r, uint32_t a) {
    asm volatile("ldmatrix.sync.aligned.m8n8.x4.trans.shared.b16 {%0,%1,%2,%3},[%4];"
        : "=r"(r[0]), "=r"(r[1]), "=r"(r[2]), "=r"(r[3]) : "r"(a));
}

// 16 rows x NT*8 cols over KS*16 k; A from smem (stride LDW), B from smem.
template <int NT, int KS>
__device__ __forceinline__ void bgemm(const uint32_t* __restrict__ As,
                                      const uint32_t* __restrict__ Ws,
                                      float acc[NT][4], int tm, int l) {
    uint32_t aAddr = s2u(As) + ((tm + (l & 7) + ((l >> 3) & 1) * 8) * LDW + ((l >> 4) & 1) * 4) * 4;
    uint32_t bAddr = s2u(Ws) + (((l & 7) + ((l >> 4) & 1) * 8) * LDW + ((l >> 3) & 1) * 4) * 4;
    #pragma unroll
    for (int ks = 0; ks < KS; ks++) {
        uint32_t a[4];
        ldsm4(a, aAddr + ks * 32);
        #pragma unroll
        for (int nq = 0; nq < NT / 2; nq++) {
            uint32_t b[4];
            ldsm4(b, bAddr + (nq * 16 * LDW) * 4 + ks * 32);
            bmma(acc[2 * nq],     a, b[0], b[1]);
            bmma(acc[2 * nq + 1], a, b[2], b[3]);
        }
    }
}

// Same, but A fragments already in registers (pa[ks][4]).
template <int NT, int KS>
__device__ __forceinline__ void bgemm_ra(const uint32_t pa[][4],
                                         const uint32_t* __restrict__ Ws,
                                         float acc[NT][4], int l) {
    uint32_t bAddr = s2u(Ws) + (((l & 7) + ((l >> 4) & 1) * 8) * LDW + ((l >> 3) & 1) * 4) * 4;
    #pragma unroll
    for (int ks = 0; ks < KS; ks++) {
        #pragma unroll
        for (int nq = 0; nq < NT / 2; nq++) {
            uint32_t b[4];
            ldsm4(b, bAddr + (nq * 16 * LDW) * 4 + ks * 32);
            bmma(acc[2 * nq],     pa[ks], b[0], b[1]);
            bmma(acc[2 * nq + 1], pa[ks], b[2], b[3]);
        }
    }
}

// ---------------------------------------------------------------------------
// K0a: weights -> bf16x2 pairs
// ---------------------------------------------------------------------------
__global__ void prep_kernel(const float* __restrict__ qkv_w, const float* __restrict__ proj_w,
                            const float* __restrict__ fc1_w, const float* __restrict__ fc2_w) {
    int i = blockIdx.x * 256 + threadIdx.x;
    if (i < 13824) {
        int r = i / 48, p = i % 48;
        gw_qkv[i] = pk(qkv_w[r * 96 + 2 * p], qkv_w[r * 96 + 2 * p + 1]);
        return;
    }
    i -= 13824;
    if (i < 4608) {
        int r = i / 48, p = i % 48;
        gw_proj[i] = pk(proj_w[r * 96 + 2 * p], proj_w[r * 96 + 2 * p + 1]);
        return;
    }
    i -= 4608;
    if (i < 18432) {
        int r = i / 48, p = i % 48;
        gw_fc1[i] = pk(fc1_w[r * 96 + 2 * p], fc1_w[r * 96 + 2 * p + 1]);
        return;
    }
    i -= 18432;
    if (i < 18432) {
        int r = i / 192, p = i % 192;
        gw_fc2[i] = pk(fc2_w[r * 384 + 2 * p], fc2_w[r * 384 + 2 * p + 1]);
    }
}

// ---------------------------------------------------------------------------
// K0b: bias gather -> bf16x2 [h][m][n/2], scaled by log2e
// ---------------------------------------------------------------------------
__global__ void bias_kernel(const float* __restrict__ bias_table) {
    int m = blockIdx.x & 255;
    int h = blockIdx.x >> 8;
    int n2 = threadIdx.x;
    int n0 = 2 * n2, n1 = 2 * n2 + 1;
    int dy0 = (n0 >> 4) - (m >> 4), dx0 = (n0 & 15) - (m & 15);
    int dy1 = (n1 >> 4) - (m >> 4), dx1 = (n1 & 15) - (m & 15);
    float b0 = bias_table[((dy0 + 15) * 31 + (dx0 + 15)) * NH + h] * LOG2E;
    float b1 = bias_table[((dy1 + 15) * 31 + (dx1 + 15)) * NH + h] * LOG2E;
    g_biasp[(h * NTOK + m) * 128 + n2] = pk(b0, b1);
}

// ---------------------------------------------------------------------------
// K1: window partition + LN1 + QKV GEMM, 128 tokens/CTA
// ---------------------------------------------------------------------------
__global__ __launch_bounds__(256, 2) void qkv_kernel(const float* __restrict__ x,
                                                     const float* __restrict__ qkv_b,
                                                     const float* __restrict__ ln_g,
                                                     const float* __restrict__ ln_b) {
    extern __shared__ uint32_t sm[];
    uint32_t* As  = sm;               // [128][LDW]
    uint32_t* Wb0 = sm + 128 * LDW;
    uint32_t* Wb1 = Wb0 + 96 * LDW;
    int bw = blockIdx.x, w = bw >> 1, half = bw & 1;
    int t = threadIdx.x, l = t & 31, wid = t >> 5, tm = wid * 16;
    int g = l >> 2, tg = l & 3;
    int b = w >> 8, hb = (w >> 4) & 15, wb = w & 15;

    for (int idx = t; idx < 96 * 12; idx += 256) {
        int r = idx / 12, c4 = idx % 12;
        cp_async16(&Wb0[r * LDW + c4 * 4], &gw_qkv[r * 48 + c4 * 4]);
    }
    CP_COMMIT;

    if (t < 128) {
        int tok = half * 128 + t;
        int d = tok >> 6, ii = (tok >> 3) & 7, jj = tok & 7;
        const float* xp = x + ((size_t)b * CH * 4 + d) * 16384 + (hb * 8 + ii) * 128 + (wb * 8 + jj);
        float row[96];
        float sum = 0.f, sq = 0.f;
        float* gt = g_t + ((size_t)w * NTOK + tok) * CH;
        #pragma unroll 4
        for (int c = 0; c < CH; c++) {
            float v = xp[(size_t)c * 65536];
            sum += v; sq += v * v;
            row[c] = v;
            gt[c] = v;
        }
        float mean = sum * (1.f / CH);
        float rstd = rsqrtf(sq * (1.f / CH) - mean * mean + 1e-5f);
        #pragma unroll
        for (int p = 0; p < 48; p++) {
            float n0 = (row[2*p]   - mean) * rstd * __ldg(ln_g + 2*p)   + __ldg(ln_b + 2*p);
            float n1 = (row[2*p+1] - mean) * rstd * __ldg(ln_g + 2*p+1) + __ldg(ln_b + 2*p+1);
            As[t * LDW + p] = pk(n0, n1);
        }
    }

    const float QS = 0.17677669529663687f * LOG2E;
    for (int chunk = 0; chunk < 3; chunk++) {
        uint32_t* Wc = (chunk & 1) ? Wb1 : Wb0;
        uint32_t* Wn = (chunk & 1) ? Wb0 : Wb1;
        CP_WAIT0;
        __syncthreads();
        if (chunk < 2) {
            for (int idx = t; idx < 96 * 12; idx += 256) {
                int r = idx / 12, c4 = idx % 12;
                cp_async16(&Wn[r * LDW + c4 * 4], &gw_qkv[((chunk + 1) * 96 + r) * 48 + c4 * 4]);
            }
            CP_COMMIT;
        }
        float acc[12][4];
        #pragma unroll
        for (int ni = 0; ni < 12; ni++)
            acc[ni][0] = acc[ni][1] = acc[ni][2] = acc[ni][3] = 0.f;
        bgemm<12, 6>(As, Wc, acc, tm, l);

        #pragma unroll
        for (int ni = 0; ni < 12; ni++) {
            int cn = ni * 8 + 2 * tg;
            int h = cn >> 5, dd = cn & 31;
            float b0v = qkv_b[chunk * CH + cn], b1v = qkv_b[chunk * CH + cn + 1];
            size_t base = ((size_t)(w * NH + h)) * NTOK;
            #pragma unroll
            for (int p = 0; p < 2; p++) {
                int row = half * 128 + tm + p * 8 + g;
                float v0 = acc[ni][2*p]   + b0v;
                float v1 = acc[ni][2*p+1] + b1v;
                uint32_t* dst = (chunk == 0) ? (uint32_t*)g_q
                              : (chunk == 1) ? (uint32_t*)g_k : (uint32_t*)g_v;
                float sc = (chunk == 0) ? QS : 1.f;
                dst[(base + row) * 16 + (dd >> 1)] = pk(v0 * sc, v1 * sc);
            }
        }
    }
}

// ---------------------------------------------------------------------------
// K2: fused attention (3 heads) + proj + residual; one CTA per 128 q-tokens
// smem words: O_s[128][52]=6656 | K_s[256][20]=5120 | V_s[256][20]=5120
// P stays in registers (C-frag -> A-frag identity). Ws overlays K_s for proj.
// ---------------------------------------------------------------------------
__global__ __launch_bounds__(256, 2) void attn_kernel(const float* __restrict__ proj_b) {
    extern __shared__ uint32_t smu[];
    uint32_t* O_s = smu;             // 6656
    uint32_t* K_s = smu + 6656;      // 5120
    uint32_t* V_s = smu + 11776;     // 5120
    uint32_t* Ws  = smu + 6656;      // overlay (proj)
    int bw = blockIdx.x, w = bw >> 1, half = bw & 1;
    int t = threadIdx.x, l = t & 31, wid = t >> 5, tm = wid * 16;
    int g = l >> 2, tg = l & 3;

    uint32_t kAddr = s2u(K_s) + (((l & 7) + ((l >> 4) & 1) * 8) * LDV + ((l >> 3) & 1) * 4) * 4;
    uint32_t vAddr = s2u(V_s) + (((l & 7) + ((l >> 3) & 1) * 8) * LDV + ((l >> 4) & 1) * 4) * 4;

    for (int h = 0; h < NH; h++) {
        size_t hbo = ((size_t)(w * NH + h)) * NTOK * HD;

        __syncthreads();  // prior head's K_s/V_s reads complete
        for (int idx = t; idx < 1024; idx += 256) {
            int m = idx >> 2, c = idx & 3;
            cp_async16(&K_s[m * LDV + c * 4], &g_k[hbo + m * 32 + c * 8]);
        }
        for (int idx = t; idx < 1024; idx += 256) {
            int m = idx >> 2, c = idx & 3;
            cp_async16(&V_s[m * LDV + c * 4], &g_v[hbo + m * 32 + c * 8]);
        }
        CP_COMMIT;

        uint32_t qa[2][4];
        {
            const uint32_t* qp = (const uint32_t*)(g_q + hbo);
            int qrow = half * 128 + tm + g;
            #pragma unroll
            for (int ks = 0; ks < 2; ks++) {
                qa[ks][0] = qp[qrow * 16 + 8 * ks + tg];
                qa[ks][1] = qp[(qrow + 8) * 16 + 8 * ks + tg];
                qa[ks][2] = qp[qrow * 16 + 8 * ks + tg + 4];
                qa[ks][3] = qp[(qrow + 8) * 16 + 8 * ks + tg + 4];
            }
        }
        CP_WAIT0;
        __syncthreads();

        float m_r[2] = {-1e30f, -1e30f}, l_r[2] = {0.f, 0.f};
        float o[4][4];
        #pragma unroll
        for (int ni = 0; ni < 4; ni++)
            o[ni][0] = o[ni][1] = o[ni][2] = o[ni][3] = 0.f;

        for (int j = 0; j < 4; j++) {
            // ---- S = Q K^T (16 x 64), log2-domain logits ----
            float s[8][4];
            #pragma unroll
            for (int ni = 0; ni < 8; ni++)
                s[ni][0] = s[ni][1] = s[ni][2] = s[ni][3] = 0.f;
            #pragma unroll
            for (int np = 0; np < 4; np++)
                #pragma unroll
                for (int ks = 0; ks < 2; ks++) {
                    uint32_t bq[4];
                    ldsm4(bq, kAddr + ((j * 64 + np * 16) * LDV + ks * 8) * 4);
                    bmma(s[2 * np],     qa[ks], bq[0], bq[1]);
                    bmma(s[2 * np + 1], qa[ks], bq[2], bq[3]);
                }
            // ---- bias + row max ----
            float mx[2] = {-1e30f, -1e30f};
            #pragma unroll
            for (int p = 0; p < 2; p++) {
                int row = half * 128 + tm + p * 8 + g;
                const uint32_t* bp = g_biasp + (h * NTOK + row) * 128 + j * 32 + tg;
                #pragma unroll
                for (int ni = 0; ni < 8; ni++) {
                    float2 bv = __bfloat1622float2(*(const __nv_bfloat162*)&bp[ni * 4]);
                    s[ni][2*p]   += bv.x;
                    s[ni][2*p+1] += bv.y;
                    mx[p] = fmaxf(mx[p], fmaxf(s[ni][2*p], s[ni][2*p+1]));
                }
            }
            float corr[2];
            #pragma unroll
            for (int p = 0; p < 2; p++) {
                mx[p] = fmaxf(mx[p], __shfl_xor_sync(0xffffffffu, mx[p], 1));
                mx[p] = fmaxf(mx[p], __shfl_xor_sync(0xffffffffu, mx[p], 2));
                float mnew = fmaxf(m_r[p], mx[p]);
                corr[p] = ex2(m_r[p] - mnew);
                m_r[p] = mnew;
                l_r[p] *= corr[p];
            }
            #pragma unroll
            for (int ni = 0; ni < 4; ni++) {
                o[ni][0] *= corr[0]; o[ni][1] *= corr[0];
                o[ni][2] *= corr[1]; o[ni][3] *= corr[1];
            }
            // ---- exp2 in-place + row sum ----
            float rsum[2] = {0.f, 0.f};
            #pragma unroll
            for (int ni = 0; ni < 8; ni++) {
                s[ni][0] = ex2(s[ni][0] - m_r[0]);
                s[ni][1] = ex2(s[ni][1] - m_r[0]);
                s[ni][2] = ex2(s[ni][2] - m_r[1]);
                s[ni][3] = ex2(s[ni][3] - m_r[1]);
                rsum[0] += s[ni][0] + s[ni][1];
                rsum[1] += s[ni][2] + s[ni][3];
            }
            #pragma unroll
            for (int p = 0; p < 2; p++) {
                rsum[p] += __shfl_xor_sync(0xffffffffu, rsum[p], 1);
                rsum[p] += __shfl_xor_sync(0xffffffffu, rsum[p], 2);
                l_r[p] += rsum[p];
            }
            // ---- P: C-frag -> A-frag in registers ----
            uint32_t pa[4][4];
            #pragma unroll
            for (int ks = 0; ks < 4; ks++) {
                pa[ks][0] = pk(s[2*ks][0],     s[2*ks][1]);
                pa[ks][1] = pk(s[2*ks][2],     s[2*ks][3]);
                pa[ks][2] = pk(s[2*ks+1][0],   s[2*ks+1][1]);
                pa[ks][3] = pk(s[2*ks+1][2],   s[2*ks+1][3]);
            }
            // ---- O += P @ V (B via ldsm.trans) ----
            #pragma unroll
            for (int ks = 0; ks < 4; ks++)
                #pragma unroll
                for (int nq = 0; nq < 2; nq++) {
                    uint32_t bv[4];
                    ldsm4t(bv, vAddr + ((j * 64 + ks * 16) * LDV + nq * 8) * 4);
                    bmma(o[2 * nq],     pa[ks], bv[0], bv[1]);
                    bmma(o[2 * nq + 1], pa[ks], bv[2], bv[3]);
                }
        }
        // ---- normalize, write O_s word-cols [h*16 .. h*16+16) ----
        float rinv[2] = {1.f / l_r[0], 1.f / l_r[1]};
        #pragma unroll
        for (int p = 0; p < 2; p++) {
            int rloc = tm + p * 8 + g;
            #pragma unroll
            for (int ni = 0; ni < 4; ni++)
                O_s[rloc * LDW + h * 16 + ni * 4 + tg] =
                    pk(o[ni][2*p] * rinv[p], o[ni][2*p+1] * rinv[p]);
        }
    }

    // ---- proj + residual ----
    __syncthreads();  // last head's K/V reads done; overlay safe
    for (int idx = t; idx < 96 * 12; idx += 256) {
        int r = idx / 12, c4 = idx % 12;
        cp_async16(&Ws[r * LDW + c4 * 4], &gw_proj[r * 48 + c4 * 4]);
    }
    CP_COMMIT;
    CP_WAIT0;
    __syncthreads();

    float acc[12][4];
    #pragma unroll
    for (int ni = 0; ni < 12; ni++)
        acc[ni][0] = acc[ni][1] = acc[ni][2] = acc[ni][3] = 0.f;
    bgemm<12, 6>(O_s, Ws, acc, tm, l);

    #pragma unroll
    for (int ni = 0; ni < 12; ni++) {
        int cn = ni * 8 + 2 * tg;
        float b0v = proj_b[cn], b1v = proj_b[cn + 1];
        #pragma unroll
        for (int p = 0; p < 2; p++) {
            int row = half * 128 + tm + p * 8 + g;
            float* tp = &g_t[((size_t)w * NTOK + row) * CH + cn];
            float2 pr = *(float2*)tp;
            pr.x += acc[ni][2*p]   + b0v;
            pr.y += acc[ni][2*p+1] + b1v;
            *(float2*)tp = pr;
        }
    }
}

// ---------------------------------------------------------------------------
// K3: fused MLP: LN2 + fc1 + GELU(regs) + fc2 + residual, 128 tokens/CTA
// smem: As[128][52] | fc1 w dbuf x2 | fc2 w dbuf x2  (no H round-trip)
// ---------------------------------------------------------------------------
__global__ __launch_bounds__(256, 2) void mlp_kernel(const float* __restrict__ ln_g,
                                                     const float* __restrict__ ln_b,
                                                     const float* __restrict__ fc1_b,
                                                     const float* __restrict__ fc2_b,
                                                     float* __restrict__ out) {
    extern __shared__ uint32_t sm[];
    uint32_t* As = sm;                                  // 6656
    uint32_t* W1[2] = {sm + 6656,              sm + 6656 + 4992};
    uint32_t* W2[2] = {sm + 6656 + 2 * 4992,   sm + 6656 + 3 * 4992};
    int bw = blockIdx.x, w = bw >> 1, half = bw & 1;
    int t = threadIdx.x, l = t & 31, wid = t >> 5, tm = wid * 16;
    int g = l >> 2, tg = l & 3;

    // prefetch chunk 0 weights (fc1 + fc2)
    for (int idx = t; idx < 96 * 12; idx += 256) {
        int r = idx / 12, c4 = idx % 12;
        cp_async16(&W1[0][r * LDW + c4 * 4], &gw_fc1[r * 48 + c4 * 4]);
        cp_async16(&W2[0][r * LDW + c4 * 4], &gw_fc2[r * 192 + c4 * 4]);
    }
    CP_COMMIT;

    if (t < 128) {
        int tok = half * 128 + t;
        const float4* tp = (const float4*)(g_t + ((size_t)w * NTOK + tok) * CH);
        float row[96];
        float sum = 0.f, sq = 0.f;
        #pragma unroll
        for (int c4 = 0; c4 < 24; c4++) {
            float4 v = tp[c4];
            row[4*c4] = v.x; row[4*c4+1] = v.y; row[4*c4+2] = v.z; row[4*c4+3] = v.w;
            sum += v.x + v.y + v.z + v.w;
            sq  += v.x*v.x + v.y*v.y + v.z*v.z + v.w*v.w;
        }
        float mean = sum * (1.f / CH);
        float rstd = rsqrtf(sq * (1.f / CH) - mean * mean + 1e-5f);
        #pragma unroll
        for (int p = 0; p < 48; p++) {
            float n0 = (row[2*p]   - mean) * rstd * __ldg(ln_g + 2*p)   + __ldg(ln_b + 2*p);
            float n1 = (row[2*p+1] - mean) * rstd * __ldg(ln_g + 2*p+1) + __ldg(ln_b + 2*p+1);
            As[t * LDW + p] = pk(n0, n1);
        }
    }

    float acc2[12][4];
    #pragma unroll
    for (int ni = 0; ni < 12; ni++)
        acc2[ni][0] = acc2[ni][1] = acc2[ni][2] = acc2[ni][3] = 0.f;

    for (int c = 0; c < 4; c++) {
        int cur = c & 1, nxt = cur ^ 1;
        CP_WAIT0;
        __syncthreads();   // chunk-c weights ready; prior reads of buf[nxt] done
        if (c < 3) {
            for (int idx = t; idx < 96 * 12; idx += 256) {
                int r = idx / 12, c4 = idx % 12;
                cp_async16(&W1[nxt][r * LDW + c4 * 4], &gw_fc1[((c + 1) * 96 + r) * 48 + c4 * 4]);
                cp_async16(&W2[nxt][r * LDW + c4 * 4], &gw_fc2[r * 192 + (c + 1) * 48 + c4 * 4]);
            }
            CP_COMMIT;
        }

        float acc1[12][4];
        #pragma unroll
        for (int ni = 0; ni < 12; ni++)
            acc1[ni][0] = acc1[ni][1] = acc1[ni][2] = acc1[ni][3] = 0.f;
        bgemm<12, 6>(As, W1[cur], acc1, tm, l);

        // GELU in registers -> fc2 A fragments (C-frag -> A-frag identity)
        uint32_t pa[6][4];
        #pragma unroll
        for (int ni = 0; ni < 12; ni++) {
            int cn = ni * 8 + 2 * tg;
            float b0v = fc1_b[c * CH + cn], b1v = fc1_b[c * CH + cn + 1];
            float v0 = acc1[ni][0] + b0v, v1 = acc1[ni][1] + b1v;
            float v2 = acc1[ni][2] + b0v, v3 = acc1[ni][3] + b1v;
            acc1[ni][0] = 0.5f * v0 * (1.f + erff(v0 * 0.70710678118654752f));
            acc1[ni][1] = 0.5f * v1 * (1.f + erff(v1 * 0.70710678118654752f));
            acc1[ni][2] = 0.5f * v2 * (1.f + erff(v2 * 0.70710678118654752f));
            acc1[ni][3] = 0.5f * v3 * (1.f + erff(v3 * 0.70710678118654752f));
        }
        #pragma unroll
        for (int ks = 0; ks < 6; ks++) {
            pa[ks][0] = pk(acc1[2*ks][0],   acc1[2*ks][1]);
            pa[ks][1] = pk(acc1[2*ks][2],   acc1[2*ks][3]);
            pa[ks][2] = pk(acc1[2*ks+1][0], acc1[2*ks+1][1]);
            pa[ks][3] = pk(acc1[2*ks+1][2], acc1[2*ks+1][3]);
        }
        bgemm_ra<12, 6>(pa, W2[cur], acc2, l);
    }

    #pragma unroll
    for (int ni = 0; ni < 12; ni++) {
        int cn = ni * 8 + 2 * tg;
        float b0v = fc2_b[cn], b1v = fc2_b[cn + 1];
        #pragma unroll
        for (int p = 0; p < 2; p++) {
            int row = half * 128 + tm + p * 8 + g;
            const float2 tr = *(const float2*)&g_t[((size_t)w * NTOK + row) * CH + cn];
            float2 v = make_float2(acc2[ni][2*p]   + b0v + tr.x,
                                   acc2[ni][2*p+1] + b1v + tr.y);
            *(float2*)&out[((size_t)w * NTOK + row) * CH + cn] = v;
        }
    }
}

// ---------------------------------------------------------------------------
extern "C" void kernel_launch(void* const* d_in, const int* in_sizes, int n_in,
                              void* d_out, int out_size) {
    (void)in_sizes; (void)n_in; (void)out_size;
    const float* x      = (const float*)d_in[0];
    const float* qkv_w  = (const float*)d_in[1];
    const float* qkv_b  = (const float*)d_in[2];
    const float* proj_w = (const float*)d_in[3];
    const float* proj_b = (const float*)d_in[4];
    const float* btab   = (const float*)d_in[5];
    const float* ln1_g  = (const float*)d_in[6];
    const float* ln1_b  = (const float*)d_in[7];
    const float* ln2_g  = (const float*)d_in[8];
    const float* ln2_b  = (const float*)d_in[9];
    const float* fc1_w  = (const float*)d_in[10];
    const float* fc1_b  = (const float*)d_in[11];
    const float* fc2_w  = (const float*)d_in[12];
    const float* fc2_b  = (const float*)d_in[13];
    float* out = (float*)d_out;

    const int smem_qkv  = (128 * LDW + 2 * 96 * LDW) * 4;    // 66560 B
    const int smem_attn = (6656 + 5120 + 5120) * 4;          // 67584 B
    const int smem_mlp  = (6656 + 4 * 4992) * 4;             // 106496 B
    cudaFuncSetAttribute(qkv_kernel,  cudaFuncAttributeMaxDynamicSharedMemorySize, smem_qkv);
    cudaFuncSetAttribute(attn_kernel, cudaFuncAttributeMaxDynamicSharedMemorySize, smem_attn);
    cudaFuncSetAttribute(mlp_kernel,  cudaFuncAttributeMaxDynamicSharedMemorySize, smem_mlp);

    prep_kernel<<<216, 256>>>(qkv_w, proj_w, fc1_w, fc2_w);
    bias_kernel<<<NH * NTOK, 128>>>(btab);
    qkv_kernel<<<NWIN * 2, 256, smem_qkv>>>(x, qkv_b, ln1_g, ln1_b);
    attn_kernel<<<NWIN * 2, 256, smem_attn>>>(proj_b);
    mlp_kernel<<<NWIN * 2, 256, smem_mlp>>>(ln2_g, ln2_b, fc1_b, fc2_b, out);
}